// round 11
// baseline (speedup 1.0000x reference)
#include <cuda_runtime.h>
#include <cuda_fp16.h>

#define NMAX   100000
#define VOCAB  32
#define NTYPE  16
#define EMB    64
#define MSGD   128
#define EEMB   32
#define CIN    (EMB + EEMB)      // 96
#define NPAIR  (VOCAB * NTYPE)   // 512
#define G3     192               // 3*EMB
#define ROWW   96                // 32-bit words per table row (384 B, no pad)
#define CAP    96                // per-node bucket capacity (multiple of 8)
#define TPB    8                 // types per table block
#define NTB    (VOCAB * (NTYPE / TPB))   // 64 table blocks

// ---------------- static scratch ----------------
__device__ __align__(16) unsigned g_tabw[NPAIR * ROWW];        // 192 KB fp16 table, L1-resident
__device__ __align__(16) float4 g_epi[VOCAB * 32 * 2];         // 32 KB fp32 epilogue
__device__ int g_deg[NMAX];                                    // zeroed via memsetAsync
__device__ __align__(16) unsigned short g_pairs2[NMAX * CAP];  // 19.2 MB buckets (store p*6)

// ---------------- fused front-end: type-blocked tables + bucket scatter ----------------
__global__ void __launch_bounds__(192) k_work(
    const int* __restrict__ nid, const int* __restrict__ src,
    const int* __restrict__ dst, const int* __restrict__ typ, int E,
    const float* __restrict__ emb, const float* __restrict__ eemb,
    const float* __restrict__ W1, const float* __restrict__ b1,
    const float* __restrict__ W2, const float* __restrict__ b2,
    const float* __restrict__ W_ih, const float* __restrict__ b_ih,
    const float* __restrict__ W_hh, const float* __restrict__ b_hh) {
    int b = blockIdx.x, tid = threadIdx.x;
    if (b < NTB) {
        __shared__ __align__(16) float xv[EMB];
        __shared__ __align__(16) float eS[EEMB * TPB];    // eS[i*TPB+t]
        __shared__ __align__(16) float base1[MSGD];
        __shared__ __align__(16) float ghs[G3];
        __shared__ __align__(16) float hidS[MSGD * TPB];  // hidS[j*TPB+t]
        __shared__ __align__(16) float msgS[MSGD * TPB];  // msgS[j*TPB+t]
        __shared__ __align__(16) float m2S[TPB * G3];     // m2S[t*G3+k]
        int v  = b >> 1;
        int t0 = (b & 1) * TPB;

        if (tid < EMB) xv[tid] = emb[v * EMB + tid];
        for (int idx = tid; idx < EEMB * TPB; idx += 192) {
            int i = idx >> 3, t = idx & 7;
            eS[idx] = eemb[(t0 + t) * EEMB + i];
        }
        __syncthreads();

        // base1 = xv @ W1[:64] + b1 (tid<128); ghs = xv @ W_hh + b_hh (all 192)
        if (tid < MSGD) {
            float s0 = b1[tid], s1 = 0.f, s2 = 0.f, s3 = 0.f;
            for (int i = 0; i < EMB; i += 4) {
                s0 += xv[i]     * W1[i * MSGD + tid];
                s1 += xv[i + 1] * W1[(i + 1) * MSGD + tid];
                s2 += xv[i + 2] * W1[(i + 2) * MSGD + tid];
                s3 += xv[i + 3] * W1[(i + 3) * MSGD + tid];
            }
            base1[tid] = (s0 + s1) + (s2 + s3);
        }
        {
            float g0 = b_hh[tid], g1 = 0.f, g2 = 0.f, g3 = 0.f;
            for (int i = 0; i < EMB; i += 4) {
                g0 += xv[i]     * W_hh[i * G3 + tid];
                g1 += xv[i + 1] * W_hh[(i + 1) * G3 + tid];
                g2 += xv[i + 2] * W_hh[(i + 2) * G3 + tid];
                g3 += xv[i + 3] * W_hh[(i + 3) * G3 + tid];
            }
            ghs[tid] = (g0 + g1) + (g2 + g3);
        }
        __syncthreads();

        // phase A: hid_t = relu(base1 + e_t @ W1[64:96])  (tid<128, 8 types in regs)
        if (tid < MSGD) {
            float acc[TPB];
            float bb = base1[tid];
            #pragma unroll
            for (int t = 0; t < TPB; t++) acc[t] = bb;
            for (int i = 0; i < EEMB; i++) {
                float w = W1[(EMB + i) * MSGD + tid];
                const float4* e4 = (const float4*)(eS + i * TPB);
                float4 e0 = e4[0], e1 = e4[1];
                acc[0] += e0.x * w; acc[1] += e0.y * w;
                acc[2] += e0.z * w; acc[3] += e0.w * w;
                acc[4] += e1.x * w; acc[5] += e1.y * w;
                acc[6] += e1.z * w; acc[7] += e1.w * w;
            }
            float4* hp = (float4*)(hidS + tid * TPB);
            float4 o0, o1;
            o0.x = fmaxf(acc[0], 0.f); o0.y = fmaxf(acc[1], 0.f);
            o0.z = fmaxf(acc[2], 0.f); o0.w = fmaxf(acc[3], 0.f);
            o1.x = fmaxf(acc[4], 0.f); o1.y = fmaxf(acc[5], 0.f);
            o1.z = fmaxf(acc[6], 0.f); o1.w = fmaxf(acc[7], 0.f);
            hp[0] = o0; hp[1] = o1;
        }
        __syncthreads();

        // phase B: msg_t = hid_t @ W2 + b2  (tid<128)
        if (tid < MSGD) {
            float acc[TPB];
            float bb = b2[tid];
            #pragma unroll
            for (int t = 0; t < TPB; t++) acc[t] = bb;
            for (int j = 0; j < MSGD; j++) {
                float w = W2[j * MSGD + tid];
                const float4* h4 = (const float4*)(hidS + j * TPB);
                float4 h0 = h4[0], h1 = h4[1];
                acc[0] += h0.x * w; acc[1] += h0.y * w;
                acc[2] += h0.z * w; acc[3] += h0.w * w;
                acc[4] += h1.x * w; acc[5] += h1.y * w;
                acc[6] += h1.z * w; acc[7] += h1.w * w;
            }
            float4* mp = (float4*)(msgS + tid * TPB);
            float4 o0, o1;
            o0.x = acc[0]; o0.y = acc[1]; o0.z = acc[2]; o0.w = acc[3];
            o1.x = acc[4]; o1.y = acc[5]; o1.z = acc[6]; o1.w = acc[7];
            mp[0] = o0; mp[1] = o1;
        }
        __syncthreads();

        // phase C: m2_t = msg_t @ W_ih  (all 192 threads)
        {
            float acc[TPB];
            #pragma unroll
            for (int t = 0; t < TPB; t++) acc[t] = 0.f;
            for (int j = 0; j < MSGD; j++) {
                float w = W_ih[j * G3 + tid];
                const float4* m4 = (const float4*)(msgS + j * TPB);
                float4 m0 = m4[0], m1 = m4[1];
                acc[0] += m0.x * w; acc[1] += m0.y * w;
                acc[2] += m0.z * w; acc[3] += m0.w * w;
                acc[4] += m1.x * w; acc[5] += m1.y * w;
                acc[6] += m1.z * w; acc[7] += m1.w * w;
            }
            #pragma unroll
            for (int t = 0; t < TPB; t++) m2S[t * G3 + tid] = acc[t];
        }
        __syncthreads();

        // pack fp16 table rows (6 warp-groups cover 8 types)
        {
            int grp = tid >> 5, lane = tid & 31;
            for (int t = grp; t < TPB; t += 6) {
                const float* m2 = m2S + t * G3;
                int p = (v << 4) | (t0 + t);
                __half2 A = __floats2half2_rn(m2[lane],      m2[lane + 96]);
                __half2 B = __floats2half2_rn(m2[lane + 32], m2[lane + 128]);
                __half2 C = __floats2half2_rn(m2[lane + 64], m2[lane + 160]);
                unsigned base = p * ROWW;
                g_tabw[base + lane * 2]     = *reinterpret_cast<unsigned*>(&A);
                g_tabw[base + lane * 2 + 1] = *reinterpret_cast<unsigned*>(&B);
                g_tabw[base + 64 + lane]    = *reinterpret_cast<unsigned*>(&C);
            }
        }
        // epilogue pack, once per v (even blocks only)
        if ((b & 1) == 0 && tid < 32) {
            int L = tid;
            float4 e0, e1;
            e0.x = ghs[L]      + b_ih[L];
            e0.y = ghs[L + 32] + b_ih[L + 32];
            e0.z = ghs[L + 64] + b_ih[L + 64];
            e0.w = ghs[L + 96] + b_ih[L + 96];
            e1.x = ghs[L + 128];
            e1.y = ghs[L + 160];
            e1.z = xv[L];
            e1.w = xv[L + 32];
            g_epi[(v * 32 + L) * 2]     = e0;
            g_epi[(v * 32 + L) * 2 + 1] = e1;
        }
    } else {
        int base = (b - NTB) * 768 + tid * 4;
        if (base + 3 < E) {
            int4 s4 = *(const int4*)(src + base);
            int4 d4 = *(const int4*)(dst + base);
            int4 t4 = *(const int4*)(typ + base);
            #pragma unroll
            for (int k = 0; k < 4; k++) {
                int d = (&d4.x)[k];
                unsigned p6 = (unsigned)(((nid[(&s4.x)[k]] << 4) | (&t4.x)[k]) * 6);
                int pos = atomicAdd(&g_deg[d], 1);
                if (pos < CAP) g_pairs2[d * CAP + pos] = (unsigned short)p6;
            }
        } else {
            for (int e = base; e < E; e++) {
                int d = dst[e];
                unsigned p6 = (unsigned)(((nid[src[e]] << 4) | typ[e]) * 6);
                int pos = atomicAdd(&g_deg[d], 1);
                if (pos < CAP) g_pairs2[d * CAP + pos] = (unsigned short)p6;
            }
        }
    }
}

// ---------------- fast activations (MUFU.TANH) ----------------
__device__ __forceinline__ float tanh_fast(float x) {
    float y;
    asm("tanh.approx.f32 %0, %1;" : "=f"(y) : "f"(x));
    return y;
}
__device__ __forceinline__ float sig_fast(float x) {
    return fmaf(tanh_fast(0.5f * x), 0.5f, 0.5f);
}

// gather one table row (p6 = pair*6; word base = p6<<4 = pair*96)
__device__ __forceinline__ void gather1(unsigned p6, int lane,
                                        __half2& q0, __half2& q1, __half2& q2) {
    const unsigned* r = g_tabw + ((unsigned)p6 << 4);
    uint2 ab = __ldg((const uint2*)r + lane);
    unsigned cc = __ldg(r + 64 + lane);
    q0 = __hadd2(q0, *reinterpret_cast<__half2*>(&ab.x));
    q1 = __hadd2(q1, *reinterpret_cast<__half2*>(&ab.y));
    q2 = __hadd2(q2, *reinterpret_cast<__half2*>(&cc));
}

// ---------------- persistent fused gather + GRU + score: one warp per node ----------------
__global__ void __launch_bounds__(256, 6) k_main(
    const int* __restrict__ nid, const float* __restrict__ b_ih,
    const float* __restrict__ score_w, const float* __restrict__ score_b,
    float* __restrict__ out, int N) {
    int lane = threadIdx.x & 31;
    int gw = (blockIdx.x * blockDim.x + threadIdx.x) >> 5;
    int stride = (gridDim.x * blockDim.x) >> 5;

    float sw0 = __ldg(&score_w[lane]);
    float sw1 = __ldg(&score_w[lane + 32]);
    float bn0 = __ldg(&b_ih[lane + 128]);
    float bn1 = __ldg(&b_ih[lane + 160]);
    float sb  = __ldg(score_b);

    for (int d = gw; d < N; d += stride) {
        int deg = __ldg(&g_deg[d]);
        int degc = min(deg, CAP);
        const unsigned short* pl = &g_pairs2[d * CAP];

        float a0 = 0.f, a1 = 0.f, a2 = 0.f, a3 = 0.f, a4 = 0.f, a5 = 0.f;

        int c = 0;
        for (; c + 8 <= degc; c += 8) {
            uint4 pk = __ldg((const uint4*)(pl + c));
            __half2 pa0 = __float2half2_rn(0.f), pa1 = pa0, pa2 = pa0;
            __half2 pb0 = pa0, pb1 = pa0, pb2 = pa0;
            unsigned w[4] = {pk.x, pk.y, pk.z, pk.w};
            #pragma unroll
            for (int q = 0; q < 4; q++) {
                gather1(w[q] & 0xFFFFu, lane, pa0, pa1, pa2);
                gather1(w[q] >> 16,     lane, pb0, pb1, pb2);
            }
            float2 f0 = __half22float2(__hadd2(pa0, pb0));
            float2 f1 = __half22float2(__hadd2(pa1, pb1));
            float2 f2 = __half22float2(__hadd2(pa2, pb2));
            a0 += f0.x; a3 += f0.y;
            a1 += f1.x; a4 += f1.y;
            a2 += f2.x; a5 += f2.y;
        }
        int m = degc - c;
        if (m > 0) {
            uint4 pk = __ldg((const uint4*)(pl + c));
            __half2 pa0 = __float2half2_rn(0.f), pa1 = pa0, pa2 = pa0;
            unsigned w[4] = {pk.x, pk.y, pk.z, pk.w};
            #pragma unroll
            for (int j = 0; j < 7; j++) {
                if (j >= m) break;
                unsigned word = w[j >> 1];
                unsigned p6 = (j & 1) ? (word >> 16) : (word & 0xFFFFu);
                gather1(p6, lane, pa0, pa1, pa2);
            }
            float2 f0 = __half22float2(pa0);
            float2 f1 = __half22float2(pa1);
            float2 f2 = __half22float2(pa2);
            a0 += f0.x; a3 += f0.y;
            a1 += f1.x; a4 += f1.y;
            a2 += f2.x; a5 += f2.y;
        }

        float inv = __fdividef(1.f, fmaxf((float)deg, 1.f));
        int v = __ldg(&nid[d]);
        float4 e0 = __ldg(&g_epi[(v * 32 + lane) * 2]);
        float4 e1 = __ldg(&g_epi[(v * 32 + lane) * 2 + 1]);

        float r0 = sig_fast(fmaf(a0, inv, e0.x));
        float r1 = sig_fast(fmaf(a1, inv, e0.y));
        float z0 = sig_fast(fmaf(a2, inv, e0.z));
        float z1 = sig_fast(fmaf(a3, inv, e0.w));
        float n0 = tanh_fast(fmaf(a4, inv, bn0) + r0 * e1.x);
        float n1 = tanh_fast(fmaf(a5, inv, bn1) + r1 * e1.y);

        float hn0 = (1.f - z0) * n0 + z0 * e1.z;
        float hn1 = (1.f - z1) * n1 + z1 * e1.w;

        float part = hn0 * sw0 + hn1 * sw1;
        #pragma unroll
        for (int o = 16; o > 0; o >>= 1) part += __shfl_down_sync(0xffffffffu, part, o);
        if (lane == 0) out[d] = part + sb;
    }
}

// ---------------- launcher ----------------
extern "C" void kernel_launch(void* const* d_in, const int* in_sizes, int n_in,
                              void* d_out, int out_size) {
    const int*   node_ids  = (const int*)  d_in[0];
    const int*   edge_src  = (const int*)  d_in[1];
    const int*   edge_dst  = (const int*)  d_in[2];
    const int*   edge_type = (const int*)  d_in[3];
    const float* emb       = (const float*)d_in[4];
    const float* eemb      = (const float*)d_in[5];
    const float* W1        = (const float*)d_in[6];
    const float* b1        = (const float*)d_in[7];
    const float* W2        = (const float*)d_in[8];
    const float* b2        = (const float*)d_in[9];
    const float* W_ih      = (const float*)d_in[10];
    const float* W_hh      = (const float*)d_in[11];
    const float* b_ih      = (const float*)d_in[12];
    const float* b_hh      = (const float*)d_in[13];
    const float* score_w   = (const float*)d_in[14];
    const float* score_b   = (const float*)d_in[15];
    float* out = (float*)d_out;

    int N = in_sizes[0];
    int E = in_sizes[1];

    void* degp = nullptr;
    cudaGetSymbolAddress(&degp, g_deg);
    cudaMemsetAsync(degp, 0, (size_t)N * sizeof(int));

    int scat_blocks = (E + 767) / 768;
    k_work<<<NTB + scat_blocks, 192>>>(
        node_ids, edge_src, edge_dst, edge_type, E,
        emb, eemb, W1, b1, W2, b2, W_ih, b_ih, W_hh, b_hh);

    k_main<<<888, 256>>>(node_ids, b_ih, score_w, score_b, out, N);
}

// round 12
// speedup vs baseline: 1.0916x; 1.0916x over previous
#include <cuda_runtime.h>
#include <cuda_fp16.h>

#define NMAX   100000
#define VOCAB  32
#define NTYPE  16
#define EMB    64
#define MSGD   128
#define EEMB   32
#define CIN    (EMB + EEMB)      // 96
#define NPAIR  (VOCAB * NTYPE)   // 512
#define G3     192               // 3*EMB
#define ROWW   96                // 32-bit words per table row (384 B, no pad)
#define CAP    96                // per-node bucket capacity (multiple of 8)

// ---------------- static scratch ----------------
// Packed fp16 gather table, 384 B/row:
//   words [0,64):  lane-major uint2 -> half2 (M2[L],M2[L+96]) , (M2[L+32],M2[L+128])
//   words [64,96): lane-major uint  -> half2 (M2[L+64],M2[L+160])
__device__ __align__(16) unsigned g_tabw[NPAIR * ROWW];        // 192 KB, L1-resident
// Per-(vocab,lane) fp32 epilogue: 2 float4 = {ghr0,ghr1,ghz0,ghz1},{ghn0,ghn1,h0,h1}
__device__ __align__(16) float4 g_epi[VOCAB * 32 * 2];         // 32 KB
__device__ int g_deg[NMAX];                                    // zeroed via memsetAsync
__device__ __align__(16) unsigned short g_pairs2[NMAX * CAP];  // 19.2 MB buckets (store p*6)

// ---------------- fused front-end: tables + bucket scatter (round-10 proven shape) ----------------
__global__ void __launch_bounds__(192) k_work(
    const int* __restrict__ nid, const int* __restrict__ src,
    const int* __restrict__ dst, const int* __restrict__ typ, int E,
    const float* __restrict__ emb, const float* __restrict__ eemb,
    const float* __restrict__ W1, const float* __restrict__ b1,
    const float* __restrict__ W2, const float* __restrict__ b2,
    const float* __restrict__ W_ih, const float* __restrict__ b_ih,
    const float* __restrict__ W_hh, const float* __restrict__ b_hh) {
    int b = blockIdx.x, tid = threadIdx.x;
    if (b < NPAIR) {
        __shared__ float x[CIN];
        __shared__ float hid[MSGD];
        __shared__ float msg[MSGD];
        __shared__ float m2[G3];
        int v = b >> 4, t = b & 15;
        if (tid < EMB)       x[tid] = emb[v * EMB + tid];
        else if (tid < CIN)  x[tid] = eemb[t * EEMB + (tid - EMB)];
        __syncthreads();
        if (tid < MSGD) {
            float s = b1[tid];
            #pragma unroll 8
            for (int i = 0; i < CIN; i++) s += x[i] * W1[i * MSGD + tid];
            hid[tid] = fmaxf(s, 0.f);
        }
        __syncthreads();
        if (tid < MSGD) {
            float m = b2[tid];
            #pragma unroll 8
            for (int i = 0; i < MSGD; i++) m += hid[i] * W2[i * MSGD + tid];
            msg[tid] = m;
        }
        __syncthreads();
        {
            float s = 0.f;
            #pragma unroll 8
            for (int j = 0; j < MSGD; j++) s += msg[j] * W_ih[j * G3 + tid];
            m2[tid] = s;
        }
        __syncthreads();
        if (tid < 32) {
            int L = tid;
            __half2 A = __floats2half2_rn(m2[L],      m2[L + 96]);
            __half2 B = __floats2half2_rn(m2[L + 32], m2[L + 128]);
            __half2 C = __floats2half2_rn(m2[L + 64], m2[L + 160]);
            unsigned base = b * ROWW;
            g_tabw[base + L * 2]     = *reinterpret_cast<unsigned*>(&A);
            g_tabw[base + L * 2 + 1] = *reinterpret_cast<unsigned*>(&B);
            g_tabw[base + 64 + L]    = *reinterpret_cast<unsigned*>(&C);
        }
    } else if (b < NPAIR + VOCAB) {
        __shared__ float h[EMB];
        __shared__ float gh[G3];
        int v = b - NPAIR;
        if (tid < EMB) h[tid] = emb[v * EMB + tid];
        __syncthreads();
        float s = b_hh[tid];
        #pragma unroll 8
        for (int j = 0; j < EMB; j++) s += h[j] * W_hh[j * G3 + tid];
        gh[tid] = s;
        __syncthreads();
        if (tid < 32) {
            int L = tid;
            float4 e0, e1;
            e0.x = gh[L]      + b_ih[L];
            e0.y = gh[L + 32] + b_ih[L + 32];
            e0.z = gh[L + 64] + b_ih[L + 64];
            e0.w = gh[L + 96] + b_ih[L + 96];
            e1.x = gh[L + 128];
            e1.y = gh[L + 160];
            e1.z = h[L];
            e1.w = h[L + 32];
            g_epi[(v * 32 + L) * 2]     = e0;
            g_epi[(v * 32 + L) * 2 + 1] = e1;
        }
    } else {
        int base = (b - NPAIR - VOCAB) * 768 + tid * 4;
        if (base + 3 < E) {
            int4 s4 = *(const int4*)(src + base);
            int4 d4 = *(const int4*)(dst + base);
            int4 t4 = *(const int4*)(typ + base);
            #pragma unroll
            for (int k = 0; k < 4; k++) {
                int d = (&d4.x)[k];
                unsigned p6 = (unsigned)(((nid[(&s4.x)[k]] << 4) | (&t4.x)[k]) * 6);
                int pos = atomicAdd(&g_deg[d], 1);
                if (pos < CAP) g_pairs2[d * CAP + pos] = (unsigned short)p6;
            }
        } else {
            for (int e = base; e < E; e++) {
                int d = dst[e];
                unsigned p6 = (unsigned)(((nid[src[e]] << 4) | typ[e]) * 6);
                int pos = atomicAdd(&g_deg[d], 1);
                if (pos < CAP) g_pairs2[d * CAP + pos] = (unsigned short)p6;
            }
        }
    }
}

// ---------------- fast activations (MUFU.TANH) ----------------
__device__ __forceinline__ float tanh_fast(float x) {
    float y;
    asm("tanh.approx.f32 %0, %1;" : "=f"(y) : "f"(x));
    return y;
}
__device__ __forceinline__ float sig_fast(float x) {
    return fmaf(tanh_fast(0.5f * x), 0.5f, 0.5f);
}

// ---------------- persistent fused gather + GRU + score: one warp per node ----------------
__global__ void __launch_bounds__(256, 6) k_main(
    const int* __restrict__ nid, const float* __restrict__ b_ih,
    const float* __restrict__ score_w, const float* __restrict__ score_b,
    float* __restrict__ out, int N) {
    int lane = threadIdx.x & 31;
    int gw = (blockIdx.x * blockDim.x + threadIdx.x) >> 5;
    int stride = (gridDim.x * blockDim.x) >> 5;

    // per-warp loop-invariant constants
    float sw0 = __ldg(&score_w[lane]);
    float sw1 = __ldg(&score_w[lane + 32]);
    float bn0 = __ldg(&b_ih[lane + 128]);
    float bn1 = __ldg(&b_ih[lane + 160]);
    float sb  = __ldg(score_b);

    // per-warp lane base pointers into the table (offset per edge = p6 << 6 bytes)
    const char* t0p = (const char*)g_tabw + lane * 8;         // uint2 slot
    const char* t1p = (const char*)g_tabw + 256 + lane * 4;   // uint slot

    for (int d = gw; d < N; d += stride) {
        int deg = __ldg(&g_deg[d]);
        int degc = min(deg, CAP);
        const unsigned short* pl = &g_pairs2[d * CAP];

        // fp16 accumulators persist across ALL chunks; single flush at the end.
        __half2 pa0 = __float2half2_rn(0.f), pa1 = pa0, pa2 = pa0;
        __half2 pb0 = pa0, pb1 = pa0, pb2 = pa0;

        int c = 0;
        for (; c + 8 <= degc; c += 8) {
            uint4 pk = __ldg((const uint4*)(pl + c));
            unsigned w[4] = {pk.x, pk.y, pk.z, pk.w};
            #pragma unroll
            for (int q = 0; q < 4; q++) {
                unsigned o0 = (w[q] & 0xFFFFu) << 6;
                unsigned o1 = (w[q] >> 16) << 6;
                uint2 ab0 = __ldg((const uint2*)(t0p + o0));
                unsigned c0 = __ldg((const unsigned*)(t1p + o0));
                uint2 ab1 = __ldg((const uint2*)(t0p + o1));
                unsigned c1 = __ldg((const unsigned*)(t1p + o1));
                pa0 = __hadd2(pa0, *reinterpret_cast<__half2*>(&ab0.x));
                pa1 = __hadd2(pa1, *reinterpret_cast<__half2*>(&ab0.y));
                pa2 = __hadd2(pa2, *reinterpret_cast<__half2*>(&c0));
                pb0 = __hadd2(pb0, *reinterpret_cast<__half2*>(&ab1.x));
                pb1 = __hadd2(pb1, *reinterpret_cast<__half2*>(&ab1.y));
                pb2 = __hadd2(pb2, *reinterpret_cast<__half2*>(&c1));
            }
        }
        // exact tail: one in-bounds uint4 pair read (CAP multiple of 8), m in [1,7]
        int m = degc - c;
        if (m > 0) {
            uint4 pk = __ldg((const uint4*)(pl + c));
            unsigned w[4] = {pk.x, pk.y, pk.z, pk.w};
            #pragma unroll
            for (int j = 0; j < 7; j++) {
                if (j >= m) break;
                unsigned word = w[j >> 1];
                unsigned off = ((j & 1) ? (word >> 16) : (word & 0xFFFFu)) << 6;
                uint2 ab = __ldg((const uint2*)(t0p + off));
                unsigned cc = __ldg((const unsigned*)(t1p + off));
                pa0 = __hadd2(pa0, *reinterpret_cast<__half2*>(&ab.x));
                pa1 = __hadd2(pa1, *reinterpret_cast<__half2*>(&ab.y));
                pa2 = __hadd2(pa2, *reinterpret_cast<__half2*>(&cc));
            }
        }
        // single flush
        float2 f0 = __half22float2(__hadd2(pa0, pb0));
        float2 f1 = __half22float2(__hadd2(pa1, pb1));
        float2 f2 = __half22float2(__hadd2(pa2, pb2));
        float a0 = f0.x, a3 = f0.y;
        float a1 = f1.x, a4 = f1.y;
        float a2 = f2.x, a5 = f2.y;

        float inv = __fdividef(1.f, fmaxf((float)deg, 1.f));
        int v = __ldg(&nid[d]);
        float4 e0 = __ldg(&g_epi[(v * 32 + lane) * 2]);
        float4 e1 = __ldg(&g_epi[(v * 32 + lane) * 2 + 1]);

        float r0 = sig_fast(fmaf(a0, inv, e0.x));
        float r1 = sig_fast(fmaf(a1, inv, e0.y));
        float z0 = sig_fast(fmaf(a2, inv, e0.z));
        float z1 = sig_fast(fmaf(a3, inv, e0.w));
        float n0 = tanh_fast(fmaf(a4, inv, bn0) + r0 * e1.x);
        float n1 = tanh_fast(fmaf(a5, inv, bn1) + r1 * e1.y);

        float hn0 = (1.f - z0) * n0 + z0 * e1.z;
        float hn1 = (1.f - z1) * n1 + z1 * e1.w;

        float part = hn0 * sw0 + hn1 * sw1;
        #pragma unroll
        for (int o = 16; o > 0; o >>= 1) part += __shfl_down_sync(0xffffffffu, part, o);
        if (lane == 0) out[d] = part + sb;
    }
}

// ---------------- launcher ----------------
extern "C" void kernel_launch(void* const* d_in, const int* in_sizes, int n_in,
                              void* d_out, int out_size) {
    const int*   node_ids  = (const int*)  d_in[0];
    const int*   edge_src  = (const int*)  d_in[1];
    const int*   edge_dst  = (const int*)  d_in[2];
    const int*   edge_type = (const int*)  d_in[3];
    const float* emb       = (const float*)d_in[4];
    const float* eemb      = (const float*)d_in[5];
    const float* W1        = (const float*)d_in[6];
    const float* b1        = (const float*)d_in[7];
    const float* W2        = (const float*)d_in[8];
    const float* b2        = (const float*)d_in[9];
    const float* W_ih      = (const float*)d_in[10];
    const float* W_hh      = (const float*)d_in[11];
    const float* b_ih      = (const float*)d_in[12];
    const float* b_hh      = (const float*)d_in[13];
    const float* score_w   = (const float*)d_in[14];
    const float* score_b   = (const float*)d_in[15];
    float* out = (float*)d_out;

    int N = in_sizes[0];
    int E = in_sizes[1];

    // zero per-node degree counters (DMA, graph-capturable)
    void* degp = nullptr;
    cudaGetSymbolAddress(&degp, g_deg);
    cudaMemsetAsync(degp, 0, (size_t)N * sizeof(int));

    int scat_blocks = (E + 767) / 768;
    k_work<<<NPAIR + VOCAB + scat_blocks, 192>>>(
        node_ids, edge_src, edge_dst, edge_type, E,
        emb, eemb, W1, b1, W2, b2, W_ih, b_ih, W_hh, b_hh);

    // persistent: 6 blocks/SM x 148 SMs
    k_main<<<888, 256>>>(node_ids, b_ih, score_w, score_b, out, N);
}